// round 10
// baseline (speedup 1.0000x reference)
#include <cuda_runtime.h>
#include <cuda_fp16.h>
#include <cstdint>
#include <cstddef>

#define THREADS 512
#define BM      64
// ---- dynamic smem layout (bytes from base) ----
#define OFF_A    0            // A tile fp16 [64][264] -> 64*528 = 33792
#define A_STR    528
#define OFF_RED  33792        // 1024 floats = 4096
#define OFF_W0   37888        // 2 weight bufs fp16 [256 rows][64 halves @ stride 144B]
#define WBSZ     36864
#define WB_STR   144
#define SMEM_NEED (37888 + 2*36864)   // 111616

// ---- precomputed weights (device globals) ----
__device__ __half  g_w1h[256*256];
__device__ __half  g_w2h[256*256];
__device__ __half  g_w3h[512*256];
__device__ __half2 g_film[256*256];   // (gamma, beta) packed fp16

// ---------------- helpers ----------------
__device__ __forceinline__ uint32_t smem_u32(const void* p){
  uint32_t a; asm("{ .reg .u64 t; cvta.to.shared.u64 t, %1; cvt.u32.u64 %0, t; }" : "=r"(a) : "l"(p));
  return a;
}
__device__ __forceinline__ float ldsf(uint32_t a){
  float v; asm volatile("ld.shared.f32 %0, [%1];" : "=f"(v) : "r"(a)); return v;
}
__device__ __forceinline__ void sts32(uint32_t a, uint32_t v){
  asm volatile("st.shared.b32 [%0], %1;" :: "r"(a), "r"(v));
}
__device__ __forceinline__ void stsf(uint32_t a, float v){
  asm volatile("st.shared.f32 [%0], %1;" :: "r"(a), "f"(v));
}
__device__ __forceinline__ void sts64(uint32_t a, uint32_t v0, uint32_t v1){
  asm volatile("st.shared.v2.b32 [%0], {%1,%2};" :: "r"(a), "r"(v0), "r"(v1));
}
__device__ __forceinline__ void cpasync16(uint32_t dst, const void* src){
  asm volatile("{ .reg .u64 gp; cvta.to.global.u64 gp, %1; cp.async.cg.shared.global [%0], [gp], 16; }"
               :: "r"(dst), "l"(src));
}
#define CPCOMMIT() asm volatile("cp.async.commit_group;" ::: "memory")
#define CPWAIT0()  asm volatile("cp.async.wait_group 0;" ::: "memory")

__device__ __forceinline__ void ldsm4(uint32_t* r, uint32_t a){
  asm volatile("ldmatrix.sync.aligned.m8n8.x4.shared.b16 {%0,%1,%2,%3}, [%4];"
    : "=r"(r[0]),"=r"(r[1]),"=r"(r[2]),"=r"(r[3]) : "r"(a));
}
__device__ __forceinline__ void mma16816(float* c, const uint32_t* a, uint32_t b0, uint32_t b1){
  asm volatile("mma.sync.aligned.m16n8k16.row.col.f32.f16.f16.f32 "
    "{%0,%1,%2,%3}, {%4,%5,%6,%7}, {%8,%9}, {%0,%1,%2,%3};"
    : "+f"(c[0]), "+f"(c[1]), "+f"(c[2]), "+f"(c[3])
    : "r"(a[0]),"r"(a[1]),"r"(a[2]),"r"(a[3]),"r"(b0),"r"(b1));
}
__device__ __forceinline__ uint32_t pack_h2(float x, float y){
  __half2 h = __floats2half2_rn(x, y);
  return *reinterpret_cast<uint32_t*>(&h);
}

// ---------------- merged precompute (ONE launch) ----------------
__global__ void pre_all(const float* __restrict__ v1, const float* __restrict__ g1,
                        const float* __restrict__ v2, const float* __restrict__ g2,
                        const float* __restrict__ v3, const float* __restrict__ g3,
                        const float* __restrict__ vc, const float* __restrict__ gc,
                        const float* __restrict__ cond, const float* __restrict__ b_cond){
  int b = blockIdx.x, tid = threadIdx.x, lane = tid & 31, wid = tid >> 5;
  const float* v; const float* gs; __half* wh = nullptr; int row; int film = 0;
  if      (b < 256)  { v=v1; gs=g1; wh=g_w1h; row=b; }
  else if (b < 512)  { v=v2; gs=g2; wh=g_w2h; row=b-256; }
  else if (b < 1024) { v=v3; gs=g3; wh=g_w3h; row=b-512; }
  else               { v=vc; gs=gc; row=b-1024; film=1; }
  float val = v[(size_t)row*256 + tid];
  float sq = val*val;
  #pragma unroll
  for (int o=16;o;o>>=1) sq += __shfl_xor_sync(0xffffffffu, sq, o);
  __shared__ float red[8]; __shared__ float s_scale; __shared__ float wrow[256];
  if (lane==0) red[tid>>5] = sq;
  __syncthreads();
  if (tid==0){
    float tot=0.f;
    #pragma unroll
    for (int i=0;i<8;i++) tot += red[i];
    s_scale = gs[row]*rsqrtf(tot);
  }
  __syncthreads();
  float o = val * s_scale;
  if (!film){ wh[(size_t)row*256 + tid] = __float2half_rn(o); return; }

  // film: j = row of wc; j<256 -> gamma col j; j>=256 -> beta col j-256
  wrow[tid] = o;
  __syncthreads();
  float w8[8];
  #pragma unroll
  for (int q=0;q<8;q++) w8[q] = wrow[lane + 32*q];
  float bc = b_cond[row];
  int j = row;
  __half* fh = reinterpret_cast<__half*>(g_film);
  #pragma unroll 1
  for (int gi=0; gi<32; gi++){
    int g = wid*32 + gi;
    const float* cp = cond + (size_t)g*256;
    float s = 0.f;
    #pragma unroll
    for (int q=0;q<8;q++) s = fmaf(w8[q], cp[lane + 32*q], s);
    #pragma unroll
    for (int o2=16;o2;o2>>=1) s += __shfl_xor_sync(0xffffffffu, s, o2);
    if (lane==0){
      float valr = s + bc;
      if (j < 256) fh[((size_t)g*256 + j)*2]           = __float2half_rn(valr + 1.f);
      else         fh[((size_t)g*256 + (j-256))*2 + 1] = __float2half_rn(valr);
    }
  }
}

// ---------------- main kernel pieces ----------------
// global chunk index 0..15 -> weight pointer (64 K-halves each), or null
__device__ __forceinline__ const __half* chunk_ptr(int i){
  if (i < 4)  return g_w1h + i*64;
  if (i < 8)  return g_w2h + (i-4)*64;
  if (i < 16){
    int j = i - 8;
    return g_w3h + (size_t)(j>>2)*(256*256) + (j&3)*64;
  }
  return nullptr;
}

// stage one [256 n x 64 k] fp16 chunk (32KB) into wbuf via cp.async
__device__ __forceinline__ void stage_async(const __half* __restrict__ base, uint32_t wbu, int tid){
  #pragma unroll
  for (int i=0;i<4;i++){
    int idx = tid + i*THREADS;          // 2048 x 16B
    int row = idx >> 3, u = idx & 7;
    cpasync16(wbu + (uint32_t)row*WB_STR + (uint32_t)u*16,
              base + (size_t)row*256 + u*8);
  }
}

// warp tile 32x32: 2 m16 x 4 n8; per k16: 2 a-ldsm4 + 2 b-ldsm4, 8 mma
__device__ __forceinline__ void mma_chunk(uint32_t aL0, uint32_t aL1,
    uint32_t bL0, uint32_t bL1, float acc[2][4][4]){
  #pragma unroll
  for (int k16=0; k16<4; k16++){
    uint32_t ko = (uint32_t)k16*32;
    uint32_t a0[4], a1[4], b0[4], b1[4];
    ldsm4(a0, aL0+ko); ldsm4(a1, aL1+ko);
    ldsm4(b0, bL0+ko); ldsm4(b1, bL1+ko);
    mma16816(acc[0][0], a0, b0[0], b0[1]);  mma16816(acc[1][0], a1, b0[0], b0[1]);
    mma16816(acc[0][1], a0, b0[2], b0[3]);  mma16816(acc[1][1], a1, b0[2], b0[3]);
    mma16816(acc[0][2], a0, b1[0], b1[1]);  mma16816(acc[1][2], a1, b1[0], b1[1]);
    mma16816(acc[0][3], a0, b1[2], b1[3]);  mma16816(acc[1][3], a1, b1[2], b1[3]);
  }
}

__device__ __forceinline__ void zacc(float acc[2][4][4]){
  #pragma unroll
  for (int i=0;i<2;i++)
    #pragma unroll
    for (int j=0;j<4;j++)
      #pragma unroll
      for (int q=0;q<4;q++) acc[i][j][q]=0.f;
}

// one chunk: wait its data (distance-1), sync, prefetch chunk i+1, mma
__device__ __forceinline__ void do_chunk(int i, uint32_t sb,
                                         const uint32_t* aL, const uint32_t* bL,
                                         float acc[2][4][4], int tid){
  CPWAIT0();
  __syncthreads();
  const __half* nw = chunk_ptr(i+1);
  if (nw) stage_async(nw, sb + OFF_W0 + (uint32_t)(((i+1)&1)*WBSZ), tid);
  CPCOMMIT();
  uint32_t wOff = (uint32_t)((i&1)*WBSZ);
  uint32_t aOff = (uint32_t)((i&3)*128);   // 64 halves per chunk
  mma_chunk(aL[0]+aOff, aL[1]+aOff, bL[0]+wOff, bL[1]+wOff, acc);
}

__global__ void __launch_bounds__(THREADS,2)
fused_kernel(const float* __restrict__ x, const int* __restrict__ bids,
             const float* __restrict__ b2, const float* __restrict__ b3,
             float* __restrict__ out, int N)
{
  extern __shared__ char smraw[];
  const uint32_t sb = smem_u32(smraw);

  const int tid = threadIdx.x, lane = tid & 31, wid = tid >> 5;
  const int wm = wid >> 3, wn = wid & 7;     // 2 x 8 warp grid, tile 32x32
  const int g = lane >> 2, t = lane & 3;
  const int rowBase = blockIdx.x * BM;

  // prefetch chunk 0
  stage_async(chunk_ptr(0), sb + OFF_W0, tid); CPCOMMIT();

  // ---- load x tile -> A smem as fp16 ----
  #pragma unroll
  for (int i=0;i<8;i++){
    int idx = tid + i*THREADS;          // 4096 float4 (64 rows x 64 units)
    int r = idx >> 6, c4 = idx & 63;
    int gr = rowBase + r;
    float4 v = *(const float4*)(x + (size_t)gr*256 + c4*4);
    sts64(sb + OFF_A + (uint32_t)r*A_STR + (uint32_t)c4*8,
          pack_h2(v.x, v.y), pack_h2(v.z, v.w));
  }

  // ldmatrix lane addressing
  const int mi = lane >> 3, r8 = lane & 7;
  uint32_t aL[2], bL[2];
  #pragma unroll
  for (int mt=0; mt<2; mt++)
    aL[mt] = sb + OFF_A + (uint32_t)((wm*32 + mt*16 + (mi&1)*8 + r8)*A_STR) + (uint32_t)((mi>>1)*16);
  #pragma unroll
  for (int n2=0; n2<2; n2++)
    bL[n2] = sb + OFF_W0 + (uint32_t)((wn*32 + n2*16 + (mi>>1)*8 + r8)*WB_STR) + (uint32_t)((mi&1)*16);

  const uint32_t redS = sb + OFF_RED;
  float acc[2][4][4];
  int ci = 0;

  // ================= GEMM1 (chunks 0..3) =================
  zacc(acc);
  #pragma unroll
  for (int i=0;i<4;i++,ci++) do_chunk(ci, sb, aL, bL, acc, tid);

  // ---- epilogue 1: layernorm + FiLM(half2) + relu -> A ----
  {
    #pragma unroll
    for (int mt=0; mt<2; mt++){
      #pragma unroll
      for (int h=0; h<2; h++){
        float S=0.f, Q=0.f;
        #pragma unroll
        for (int nt=0; nt<4; nt++){
          float u = acc[mt][nt][2*h], v = acc[mt][nt][2*h+1];
          S += u + v; Q = fmaf(u,u,Q); Q = fmaf(v,v,Q);
        }
        S += __shfl_xor_sync(0xffffffffu, S, 1); S += __shfl_xor_sync(0xffffffffu, S, 2);
        Q += __shfl_xor_sync(0xffffffffu, Q, 1); Q += __shfl_xor_sync(0xffffffffu, Q, 2);
        int r = wm*32 + mt*16 + h*8 + g;
        if (t==0){
          stsf(redS + (uint32_t)(r*8 + wn)*4,        S);
          stsf(redS + (uint32_t)(512 + r*8 + wn)*4,  Q);
        }
      }
    }
    __syncthreads();
    #pragma unroll
    for (int mt=0; mt<2; mt++){
      #pragma unroll
      for (int h=0; h<2; h++){
        int r = wm*32 + mt*16 + h*8 + g;
        float S=0.f, Q=0.f;
        #pragma unroll
        for (int c=0;c<8;c++){
          S += ldsf(redS + (uint32_t)(r*8 + c)*4);
          Q += ldsf(redS + (uint32_t)(512 + r*8 + c)*4);
        }
        float mu = S*(1.f/256.f);
        float var = fmaf(-mu, mu, Q*(1.f/256.f));
        float rs = rsqrtf(var + 1e-5f);
        int bi = __ldg(bids + rowBase + r);
        const __half2* fp = g_film + (size_t)bi*256 + wn*32 + 2*t;
        #pragma unroll
        for (int nt=0; nt<4; nt++){
          uint2 raw = *(const uint2*)(fp + nt*8);      // 2 x (gamma,beta)
          float2 f0 = __half22float2(*reinterpret_cast<__half2*>(&raw.x));
          float2 f1 = __half22float2(*reinterpret_cast<__half2*>(&raw.y));
          float v0 = fmaxf(fmaf((acc[mt][nt][2*h  ]-mu)*rs, f0.x, f0.y), 0.f);
          float v1 = fmaxf(fmaf((acc[mt][nt][2*h+1]-mu)*rs, f1.x, f1.y), 0.f);
          sts32(sb + OFF_A + (uint32_t)r*A_STR + (uint32_t)(wn*32+nt*8+2*t)*2,
                pack_h2(v0, v1));
        }
      }
    }
    __syncthreads();
  }

  // ================= GEMM2 (chunks 4..7) =================
  zacc(acc);
  #pragma unroll
  for (int i=0;i<4;i++,ci++) do_chunk(ci, sb, aL, bL, acc, tid);

  // ---- epilogue 2: relu(acc + b2) -> A ----
  {
    float2 bb[4];
    #pragma unroll
    for (int nt=0; nt<4; nt++) bb[nt] = *(const float2*)(b2 + wn*32 + nt*8 + 2*t);
    __syncthreads();
    #pragma unroll
    for (int mt=0; mt<2; mt++){
      #pragma unroll
      for (int h=0; h<2; h++){
        int r = wm*32 + mt*16 + h*8 + g;
        #pragma unroll
        for (int nt=0; nt<4; nt++){
          float v0 = fmaxf(acc[mt][nt][2*h  ] + bb[nt].x, 0.f);
          float v1 = fmaxf(acc[mt][nt][2*h+1] + bb[nt].y, 0.f);
          sts32(sb + OFF_A + (uint32_t)r*A_STR + (uint32_t)(wn*32+nt*8+2*t)*2,
                pack_h2(v0, v1));
        }
      }
    }
    __syncthreads();
  }

  // ================= GEMM3 half A (chunks 8..11) =================
  zacc(acc);
  #pragma unroll
  for (int i=0;i<4;i++,ci++) do_chunk(ci, sb, aL, bL, acc, tid);
  {
    float2 bb[4];
    #pragma unroll
    for (int nt=0; nt<4; nt++) bb[nt] = *(const float2*)(b3 + wn*32 + nt*8 + 2*t);
    #pragma unroll
    for (int mt=0; mt<2; mt++){
      #pragma unroll
      for (int h=0; h<2; h++){
        int gr = rowBase + wm*32 + mt*16 + h*8 + g;
        #pragma unroll
        for (int nt=0; nt<4; nt++){
          float2 o = make_float2(acc[mt][nt][2*h] + bb[nt].x,
                                 acc[mt][nt][2*h+1] + bb[nt].y);
          *(float2*)(out + (size_t)gr*512 + wn*32 + nt*8 + 2*t) = o;
        }
      }
    }
  }

  // ================= GEMM3 half B (chunks 12..15) =================
  zacc(acc);
  #pragma unroll
  for (int i=0;i<4;i++,ci++) do_chunk(ci, sb, aL, bL, acc, tid);
  {
    float2 bb[4];
    #pragma unroll
    for (int nt=0; nt<4; nt++) bb[nt] = *(const float2*)(b3 + 256 + wn*32 + nt*8 + 2*t);
    #pragma unroll
    for (int mt=0; mt<2; mt++){
      #pragma unroll
      for (int h=0; h<2; h++){
        int gr = rowBase + wm*32 + mt*16 + h*8 + g;
        #pragma unroll
        for (int nt=0; nt<4; nt++){
          float2 o = make_float2(acc[mt][nt][2*h] + bb[nt].x,
                                 acc[mt][nt][2*h+1] + bb[nt].y);
          *(float2*)(out + (size_t)gr*512 + 256 + wn*32 + nt*8 + 2*t) = o;
        }
      }
    }
  }
}

// ---------------- launch ----------------
extern "C" void kernel_launch(void* const* d_in, const int* in_sizes, int n_in,
                              void* d_out, int out_size){
  const float* x      = (const float*)d_in[0];
  const float* cond   = (const float*)d_in[1];
  const int*   bids   = (const int*)  d_in[2];
  const float* v_cond = (const float*)d_in[3];
  const float* g_cond = (const float*)d_in[4];
  const float* b_cond = (const float*)d_in[5];
  const float* v1     = (const float*)d_in[6];
  const float* g1     = (const float*)d_in[7];
  const float* v2     = (const float*)d_in[8];
  const float* g2     = (const float*)d_in[9];
  const float* b2     = (const float*)d_in[10];
  const float* v3     = (const float*)d_in[11];
  const float* g3     = (const float*)d_in[12];
  const float* b3     = (const float*)d_in[13];
  float* out = (float*)d_out;
  int N = in_sizes[0] / 256;

  pre_all<<<1536,256>>>(v1,g1, v2,g2, v3,g3, v_cond,g_cond, cond, b_cond);

  cudaFuncSetAttribute(fused_kernel, cudaFuncAttributeMaxDynamicSharedMemorySize, SMEM_NEED);
  int blocks = (N + BM - 1) / BM;
  fused_kernel<<<blocks, THREADS, SMEM_NEED>>>(x, bids, b2, b3, out, N);
}

// round 11
// speedup vs baseline: 1.1109x; 1.1109x over previous
#include <cuda_runtime.h>
#include <cuda_fp16.h>
#include <cstdint>
#include <cstddef>

#define THREADS 256
#define BM      64
// ---- dynamic smem layout (bytes from base) ----
#define OFF_A    0            // A tile fp16 [64][264] -> 64*528 = 33792
#define A_STR    528
#define OFF_RED  33792        // 512 floats = 2048
#define OFF_W0   35840        // 2 weight bufs fp16 [256 rows][64 halves @ stride 144B]
#define WBSZ     36864
#define WB_STR   144
#define SMEM_NEED (35840 + 2*36864)   // 109568

// ---- precomputed weights (device globals) ----
__device__ __half  g_w1h[256*256];
__device__ __half  g_w2h[256*256];
__device__ __half  g_w3h[512*256];
__device__ __half2 g_film[256*256];   // (gamma, beta) packed fp16

// ---------------- helpers ----------------
__device__ __forceinline__ uint32_t smem_u32(const void* p){
  uint32_t a; asm("{ .reg .u64 t; cvta.to.shared.u64 t, %1; cvt.u32.u64 %0, t; }" : "=r"(a) : "l"(p));
  return a;
}
__device__ __forceinline__ float ldsf(uint32_t a){
  float v; asm volatile("ld.shared.f32 %0, [%1];" : "=f"(v) : "r"(a)); return v;
}
__device__ __forceinline__ void sts32(uint32_t a, uint32_t v){
  asm volatile("st.shared.b32 [%0], %1;" :: "r"(a), "r"(v));
}
__device__ __forceinline__ void stsf(uint32_t a, float v){
  asm volatile("st.shared.f32 [%0], %1;" :: "r"(a), "f"(v));
}
__device__ __forceinline__ void sts64(uint32_t a, uint32_t v0, uint32_t v1){
  asm volatile("st.shared.v2.b32 [%0], {%1,%2};" :: "r"(a), "r"(v0), "r"(v1));
}
__device__ __forceinline__ void cpasync16(uint32_t dst, const void* src){
  asm volatile("{ .reg .u64 gp; cvta.to.global.u64 gp, %1; cp.async.cg.shared.global [%0], [gp], 16; }"
               :: "r"(dst), "l"(src));
}
#define CPCOMMIT() asm volatile("cp.async.commit_group;" ::: "memory")
#define CPWAIT0()  asm volatile("cp.async.wait_group 0;" ::: "memory")

__device__ __forceinline__ void ldsm4(uint32_t* r, uint32_t a){
  asm volatile("ldmatrix.sync.aligned.m8n8.x4.shared.b16 {%0,%1,%2,%3}, [%4];"
    : "=r"(r[0]),"=r"(r[1]),"=r"(r[2]),"=r"(r[3]) : "r"(a));
}
__device__ __forceinline__ void mma16816(float* c, const uint32_t* a, uint32_t b0, uint32_t b1){
  asm volatile("mma.sync.aligned.m16n8k16.row.col.f32.f16.f16.f32 "
    "{%0,%1,%2,%3}, {%4,%5,%6,%7}, {%8,%9}, {%0,%1,%2,%3};"
    : "+f"(c[0]), "+f"(c[1]), "+f"(c[2]), "+f"(c[3])
    : "r"(a[0]),"r"(a[1]),"r"(a[2]),"r"(a[3]),"r"(b0),"r"(b1));
}
__device__ __forceinline__ uint32_t pack_h2(float x, float y){
  __half2 h = __floats2half2_rn(x, y);
  return *reinterpret_cast<uint32_t*>(&h);
}

// ---------------- merged precompute (ONE launch) ----------------
__global__ void pre_all(const float* __restrict__ v1, const float* __restrict__ g1,
                        const float* __restrict__ v2, const float* __restrict__ g2,
                        const float* __restrict__ v3, const float* __restrict__ g3,
                        const float* __restrict__ vc, const float* __restrict__ gc,
                        const float* __restrict__ cond, const float* __restrict__ b_cond){
  int b = blockIdx.x, tid = threadIdx.x, lane = tid & 31, wid = tid >> 5;
  const float* v; const float* gs; __half* wh = nullptr; int row; int film = 0;
  if      (b < 256)  { v=v1; gs=g1; wh=g_w1h; row=b; }
  else if (b < 512)  { v=v2; gs=g2; wh=g_w2h; row=b-256; }
  else if (b < 1024) { v=v3; gs=g3; wh=g_w3h; row=b-512; }
  else               { v=vc; gs=gc; row=b-1024; film=1; }
  float val = v[(size_t)row*256 + tid];
  float sq = val*val;
  #pragma unroll
  for (int o=16;o;o>>=1) sq += __shfl_xor_sync(0xffffffffu, sq, o);
  __shared__ float red[8]; __shared__ float s_scale; __shared__ float wrow[256];
  if (lane==0) red[tid>>5] = sq;
  __syncthreads();
  if (tid==0){
    float tot=0.f;
    #pragma unroll
    for (int i=0;i<8;i++) tot += red[i];
    s_scale = gs[row]*rsqrtf(tot);
  }
  __syncthreads();
  float o = val * s_scale;
  if (!film){ wh[(size_t)row*256 + tid] = __float2half_rn(o); return; }

  // film: j = row of wc; j<256 -> gamma col j; j>=256 -> beta col j-256
  wrow[tid] = o;
  __syncthreads();
  float w8[8];
  #pragma unroll
  for (int q=0;q<8;q++) w8[q] = wrow[lane + 32*q];
  float bc = b_cond[row];
  int j = row;
  __half* fh = reinterpret_cast<__half*>(g_film);
  #pragma unroll 1
  for (int gi=0; gi<32; gi++){
    int g = wid*32 + gi;
    const float* cp = cond + (size_t)g*256;
    float s = 0.f;
    #pragma unroll
    for (int q=0;q<8;q++) s = fmaf(w8[q], cp[lane + 32*q], s);
    #pragma unroll
    for (int o2=16;o2;o2>>=1) s += __shfl_xor_sync(0xffffffffu, s, o2);
    if (lane==0){
      float valr = s + bc;
      if (j < 256) fh[((size_t)g*256 + j)*2]           = __float2half_rn(valr + 1.f);
      else         fh[((size_t)g*256 + (j-256))*2 + 1] = __float2half_rn(valr);
    }
  }
}

// ---------------- main kernel pieces ----------------
// global chunk index 0..15 -> weight pointer (64 K-halves each), or null
__device__ __forceinline__ const __half* chunk_ptr(int i){
  if (i < 4)  return g_w1h + i*64;
  if (i < 8)  return g_w2h + (i-4)*64;
  if (i < 16){
    int j = i - 8;
    return g_w3h + (size_t)(j>>2)*(256*256) + (j&3)*64;
  }
  return nullptr;
}

// stage one [256 n x 64 k] fp16 chunk (32KB) into wbuf via cp.async
__device__ __forceinline__ void stage_async(const __half* __restrict__ base, uint32_t wbu, int tid){
  #pragma unroll
  for (int i=0;i<8;i++){
    int idx = tid + i*THREADS;          // 2048 x 16B
    int row = idx >> 3, u = idx & 7;
    cpasync16(wbu + (uint32_t)row*WB_STR + (uint32_t)u*16,
              base + (size_t)row*256 + u*8);
  }
}

// K=64 chunk: explicit software-pipelined fragments (double-buffered ldsm)
__device__ __forceinline__ void mma_chunk(uint32_t aL0, uint32_t aL1,
    uint32_t bL0, uint32_t bL1, uint32_t bL2, uint32_t bL3, float acc[2][8][4]){
  uint32_t a[2][2][4], b[2][4][4];
  // preload k16 = 0
  ldsm4(a[0][0], aL0); ldsm4(a[0][1], aL1);
  ldsm4(b[0][0], bL0); ldsm4(b[0][1], bL1); ldsm4(b[0][2], bL2); ldsm4(b[0][3], bL3);
  #pragma unroll
  for (int k16=0; k16<4; k16++){
    const int cur = k16 & 1, nxt = cur ^ 1;
    if (k16 < 3){
      uint32_t ko = (uint32_t)(k16+1)*32;
      ldsm4(a[nxt][0], aL0+ko); ldsm4(a[nxt][1], aL1+ko);
      ldsm4(b[nxt][0], bL0+ko); ldsm4(b[nxt][1], bL1+ko);
      ldsm4(b[nxt][2], bL2+ko); ldsm4(b[nxt][3], bL3+ko);
    }
    mma16816(acc[0][0], a[cur][0], b[cur][0][0], b[cur][0][1]);
    mma16816(acc[1][0], a[cur][1], b[cur][0][0], b[cur][0][1]);
    mma16816(acc[0][1], a[cur][0], b[cur][0][2], b[cur][0][3]);
    mma16816(acc[1][1], a[cur][1], b[cur][0][2], b[cur][0][3]);
    mma16816(acc[0][2], a[cur][0], b[cur][1][0], b[cur][1][1]);
    mma16816(acc[1][2], a[cur][1], b[cur][1][0], b[cur][1][1]);
    mma16816(acc[0][3], a[cur][0], b[cur][1][2], b[cur][1][3]);
    mma16816(acc[1][3], a[cur][1], b[cur][1][2], b[cur][1][3]);
    mma16816(acc[0][4], a[cur][0], b[cur][2][0], b[cur][2][1]);
    mma16816(acc[1][4], a[cur][1], b[cur][2][0], b[cur][2][1]);
    mma16816(acc[0][5], a[cur][0], b[cur][2][2], b[cur][2][3]);
    mma16816(acc[1][5], a[cur][1], b[cur][2][2], b[cur][2][3]);
    mma16816(acc[0][6], a[cur][0], b[cur][3][0], b[cur][3][1]);
    mma16816(acc[1][6], a[cur][1], b[cur][3][0], b[cur][3][1]);
    mma16816(acc[0][7], a[cur][0], b[cur][3][2], b[cur][3][3]);
    mma16816(acc[1][7], a[cur][1], b[cur][3][2], b[cur][3][3]);
  }
}

__device__ __forceinline__ void zacc(float acc[2][8][4]){
  #pragma unroll
  for (int i=0;i<2;i++)
    #pragma unroll
    for (int j=0;j<8;j++)
      #pragma unroll
      for (int q=0;q<4;q++) acc[i][j][q]=0.f;
}

// one chunk: wait its data (distance-1), sync, prefetch chunk i+1, mma
__device__ __forceinline__ void do_chunk(int i, uint32_t sb,
                                         const uint32_t* aL, const uint32_t* bL,
                                         float acc[2][8][4], int tid){
  CPWAIT0();
  __syncthreads();
  const __half* nw = chunk_ptr(i+1);
  if (nw) stage_async(nw, sb + OFF_W0 + (uint32_t)(((i+1)&1)*WBSZ), tid);
  CPCOMMIT();
  uint32_t wOff = (uint32_t)((i&1)*WBSZ);
  uint32_t aOff = (uint32_t)((i&3)*128);   // 64 halves per chunk
  mma_chunk(aL[0]+aOff, aL[1]+aOff,
            bL[0]+wOff, bL[1]+wOff, bL[2]+wOff, bL[3]+wOff, acc);
}

__global__ void __launch_bounds__(THREADS,2)
fused_kernel(const float* __restrict__ x, const int* __restrict__ bids,
             const float* __restrict__ b2, const float* __restrict__ b3,
             float* __restrict__ out, int N)
{
  extern __shared__ char smraw[];
  const uint32_t sb = smem_u32(smraw);

  const int tid = threadIdx.x, lane = tid & 31, wid = tid >> 5;
  const int wm = wid >> 2, wn = wid & 3;
  const int g = lane >> 2, t = lane & 3;
  const int rowBase = blockIdx.x * BM;

  // prefetch chunk 0
  stage_async(chunk_ptr(0), sb + OFF_W0, tid); CPCOMMIT();

  // ---- load x tile -> A smem as fp16 ----
  #pragma unroll
  for (int i=0;i<16;i++){
    int idx = tid + i*THREADS;          // 4096 float4 (64 rows x 64 units)
    int r = idx >> 6, c4 = idx & 63;
    int gr = rowBase + r;
    float4 v = *(const float4*)(x + (size_t)gr*256 + c4*4);
    sts64(sb + OFF_A + (uint32_t)r*A_STR + (uint32_t)c4*8,
          pack_h2(v.x, v.y), pack_h2(v.z, v.w));
  }

  // ldmatrix lane addressing
  const int mi = lane >> 3, r8 = lane & 7;
  uint32_t aL[2], bL[4];
  #pragma unroll
  for (int mt=0; mt<2; mt++)
    aL[mt] = sb + OFF_A + (uint32_t)((wm*32 + mt*16 + (mi&1)*8 + r8)*A_STR) + (uint32_t)((mi>>1)*16);
  #pragma unroll
  for (int n2=0; n2<4; n2++)
    bL[n2] = sb + OFF_W0 + (uint32_t)((wn*64 + n2*16 + (mi>>1)*8 + r8)*WB_STR) + (uint32_t)((mi&1)*16);

  const uint32_t redS = sb + OFF_RED;
  float acc[2][8][4];
  int ci = 0;

  // ================= GEMM1 (chunks 0..3) =================
  zacc(acc);
  #pragma unroll
  for (int i=0;i<4;i++,ci++) do_chunk(ci, sb, aL, bL, acc, tid);

  // ---- epilogue 1: layernorm + FiLM(half2) + relu -> A ----
  {
    #pragma unroll
    for (int mt=0; mt<2; mt++){
      #pragma unroll
      for (int h=0; h<2; h++){
        float S=0.f, Q=0.f;
        #pragma unroll
        for (int nt=0; nt<8; nt++){
          float u = acc[mt][nt][2*h], v = acc[mt][nt][2*h+1];
          S += u + v; Q = fmaf(u,u,Q); Q = fmaf(v,v,Q);
        }
        S += __shfl_xor_sync(0xffffffffu, S, 1); S += __shfl_xor_sync(0xffffffffu, S, 2);
        Q += __shfl_xor_sync(0xffffffffu, Q, 1); Q += __shfl_xor_sync(0xffffffffu, Q, 2);
        int r = wm*32 + mt*16 + h*8 + g;
        if (t==0){
          stsf(redS + (uint32_t)(r*4 + wn)*4,       S);
          stsf(redS + (uint32_t)(256 + r*4 + wn)*4, Q);
        }
      }
    }
    __syncthreads();
    #pragma unroll
    for (int mt=0; mt<2; mt++){
      #pragma unroll
      for (int h=0; h<2; h++){
        int r = wm*32 + mt*16 + h*8 + g;
        float S = ldsf(redS + (uint32_t)(r*4)*4)      + ldsf(redS + (uint32_t)(r*4+1)*4)
                + ldsf(redS + (uint32_t)(r*4+2)*4)    + ldsf(redS + (uint32_t)(r*4+3)*4);
        float Q = ldsf(redS + (uint32_t)(256+r*4)*4)  + ldsf(redS + (uint32_t)(256+r*4+1)*4)
                + ldsf(redS + (uint32_t)(256+r*4+2)*4)+ ldsf(redS + (uint32_t)(256+r*4+3)*4);
        float mu = S*(1.f/256.f);
        float var = fmaf(-mu, mu, Q*(1.f/256.f));
        float rs = rsqrtf(var + 1e-5f);
        int bi = __ldg(bids + rowBase + r);
        const __half2* fp = g_film + (size_t)bi*256 + wn*64 + 2*t;
        #pragma unroll
        for (int nt=0; nt<8; nt++){
          uint2 raw = *(const uint2*)(fp + nt*8);      // 2 x (gamma,beta)
          float2 f0 = __half22float2(*reinterpret_cast<__half2*>(&raw.x));
          float2 f1 = __half22float2(*reinterpret_cast<__half2*>(&raw.y));
          float v0 = fmaxf(fmaf((acc[mt][nt][2*h  ]-mu)*rs, f0.x, f0.y), 0.f);
          float v1 = fmaxf(fmaf((acc[mt][nt][2*h+1]-mu)*rs, f1.x, f1.y), 0.f);
          sts32(sb + OFF_A + (uint32_t)r*A_STR + (uint32_t)(wn*64+nt*8+2*t)*2,
                pack_h2(v0, v1));
        }
      }
    }
    __syncthreads();
  }

  // ================= GEMM2 (chunks 4..7) =================
  zacc(acc);
  #pragma unroll
  for (int i=0;i<4;i++,ci++) do_chunk(ci, sb, aL, bL, acc, tid);

  // ---- epilogue 2: relu(acc + b2) -> A ----
  {
    float2 bb[8];
    #pragma unroll
    for (int nt=0; nt<8; nt++) bb[nt] = *(const float2*)(b2 + wn*64 + nt*8 + 2*t);
    // barrier: A rewrite below must not race other warps' pending GEMM2 reads
    __syncthreads();
    #pragma unroll
    for (int mt=0; mt<2; mt++){
      #pragma unroll
      for (int h=0; h<2; h++){
        int r = wm*32 + mt*16 + h*8 + g;
        #pragma unroll
        for (int nt=0; nt<8; nt++){
          float v0 = fmaxf(acc[mt][nt][2*h  ] + bb[nt].x, 0.f);
          float v1 = fmaxf(acc[mt][nt][2*h+1] + bb[nt].y, 0.f);
          sts32(sb + OFF_A + (uint32_t)r*A_STR + (uint32_t)(wn*64+nt*8+2*t)*2,
                pack_h2(v0, v1));
        }
      }
    }
    __syncthreads();
  }

  // ================= GEMM3 half A (chunks 8..11) =================
  zacc(acc);
  #pragma unroll
  for (int i=0;i<4;i++,ci++) do_chunk(ci, sb, aL, bL, acc, tid);
  {
    float2 bb[8];
    #pragma unroll
    for (int nt=0; nt<8; nt++) bb[nt] = *(const float2*)(b3 + wn*64 + nt*8 + 2*t);
    #pragma unroll
    for (int mt=0; mt<2; mt++){
      #pragma unroll
      for (int h=0; h<2; h++){
        int gr = rowBase + wm*32 + mt*16 + h*8 + g;
        #pragma unroll
        for (int nt=0; nt<8; nt++){
          float2 o = make_float2(acc[mt][nt][2*h] + bb[nt].x,
                                 acc[mt][nt][2*h+1] + bb[nt].y);
          *(float2*)(out + (size_t)gr*512 + wn*64 + nt*8 + 2*t) = o;
        }
      }
    }
  }

  // ================= GEMM3 half B (chunks 12..15) =================
  zacc(acc);
  #pragma unroll
  for (int i=0;i<4;i++,ci++) do_chunk(ci, sb, aL, bL, acc, tid);
  {
    float2 bb[8];
    #pragma unroll
    for (int nt=0; nt<8; nt++) bb[nt] = *(const float2*)(b3 + 256 + wn*64 + nt*8 + 2*t);
    #pragma unroll
    for (int mt=0; mt<2; mt++){
      #pragma unroll
      for (int h=0; h<2; h++){
        int gr = rowBase + wm*32 + mt*16 + h*8 + g;
        #pragma unroll
        for (int nt=0; nt<8; nt++){
          float2 o = make_float2(acc[mt][nt][2*h] + bb[nt].x,
                                 acc[mt][nt][2*h+1] + bb[nt].y);
          *(float2*)(out + (size_t)gr*512 + 256 + wn*64 + nt*8 + 2*t) = o;
        }
      }
    }
  }
}

// ---------------- launch ----------------
extern "C" void kernel_launch(void* const* d_in, const int* in_sizes, int n_in,
                              void* d_out, int out_size){
  const float* x      = (const float*)d_in[0];
  const float* cond   = (const float*)d_in[1];
  const int*   bids   = (const int*)  d_in[2];
  const float* v_cond = (const float*)d_in[3];
  const float* g_cond = (const float*)d_in[4];
  const float* b_cond = (const float*)d_in[5];
  const float* v1     = (const float*)d_in[6];
  const float* g1     = (const float*)d_in[7];
  const float* v2     = (const float*)d_in[8];
  const float* g2     = (const float*)d_in[9];
  const float* b2     = (const float*)d_in[10];
  const float* v3     = (const float*)d_in[11];
  const float* g3     = (const float*)d_in[12];
  const float* b3     = (const float*)d_in[13];
  float* out = (float*)d_out;
  int N = in_sizes[0] / 256;

  pre_all<<<1536,256>>>(v1,g1, v2,g2, v3,g3, v_cond,g_cond, cond, b_cond);

  cudaFuncSetAttribute(fused_kernel, cudaFuncAttributeMaxDynamicSharedMemorySize, SMEM_NEED);
  int blocks = (N + BM - 1) / BM;
  fused_kernel<<<blocks, THREADS, SMEM_NEED>>>(x, bids, b2, b3, out, N);
}